// round 4
// baseline (speedup 1.0000x reference)
#include <cuda_runtime.h>

// RoiPooling: torchvision roi_pool (max), OUT=7x7, SCALE=0.125
// input:  (4, 256, 100, 152) fp32 NCHW
// boxes:  (K, 5) fp32  [batch_idx, x1, y1, x2, y2] image coords
// output: (K, 256, 7, 7) fp32
//
// KEY SEMANTIC: XLA rewrites (x / 7.0f) -> x * (1/7.0f). To bit-match the
// JAX reference we must compute bin sizes as a multiply by the correctly
// rounded fp32 reciprocal of 7, NOT an IEEE division.

static constexpr int C_  = 256;
static constexpr int H_  = 100;
static constexpr int W_  = 152;
static constexpr int HW_ = H_ * W_;

__global__ __launch_bounds__(256)
void roi_pool_direct(const float* __restrict__ x,
                     const float* __restrict__ boxes,
                     float* __restrict__ out,
                     int total)
{
    const int o = blockIdx.x * blockDim.x + threadIdx.x;
    if (o >= total) return;

    const int bin = o % 49;            // ph*7 + pw
    const int c   = (o / 49) % C_;
    const int k   = o / (49 * C_);
    const int pw  = bin % 7;
    const int ph  = bin / 7;

    const float* bx = boxes + (size_t)k * 5;
    const int b  = (int)bx[0];
    // jnp.round = round-half-to-even; *0.125f is exact (power of two)
    const int x1 = __float2int_rn(__fmul_rn(bx[1], 0.125f));
    const int y1 = __float2int_rn(__fmul_rn(bx[2], 0.125f));
    const int x2 = __float2int_rn(__fmul_rn(bx[3], 0.125f));
    const int y2 = __float2int_rn(__fmul_rn(bx[4], 0.125f));
    const int roi_w = max(x2 - x1 + 1, 1);
    const int roi_h = max(y2 - y1 + 1, 1);

    // XLA: divide-by-constant -> multiply-by-reciprocal (fp32, RN constant).
    const float RCP7 = 1.0f / 7.0f;    // constant-folded, correctly rounded
    const float bin_h = __fmul_rn((float)roi_h, RCP7);
    const float bin_w = __fmul_rn((float)roi_w, RCP7);

    const int hs = min(max((int)floorf(__fmul_rn((float)ph, bin_h)) + y1, 0), H_);
    const int he = min(max((int)ceilf (__fmul_rn((float)(ph + 1), bin_h)) + y1, 0), H_);
    const int ws = min(max((int)floorf(__fmul_rn((float)pw, bin_w)) + x1, 0), W_);
    const int we = min(max((int)ceilf (__fmul_rn((float)(pw + 1), bin_w)) + x1, 0), W_);

    const float* p = x + ((size_t)b * C_ + c) * HW_;

    float m = __int_as_float(0xff800000);   // -inf
    for (int r = hs; r < he; ++r) {
        const float* row = p + r * W_;
        for (int cc = ws; cc < we; ++cc)
            m = fmaxf(m, __ldg(row + cc));
    }

    const bool empty = (he <= hs) || (we <= ws);
    out[o] = empty ? 0.0f : m;
}

extern "C" void kernel_launch(void* const* d_in, const int* in_sizes, int n_in,
                              void* d_out, int out_size) {
    const float* x     = (const float*)d_in[0];
    const float* boxes = (const float*)d_in[1];
    float*       out   = (float*)d_out;
    const int total = out_size;                       // K * 256 * 49
    const int blocks = (total + 255) / 256;
    roi_pool_direct<<<blocks, 256>>>(x, boxes, out, total);
}